// round 16
// baseline (speedup 1.0000x reference)
#include <cuda_runtime.h>
#include <cuda_bf16.h>
#include <cstdint>
#include <math.h>

// Problem constants
#define NB 64
#define NT 512
#define NF 256
#define NP 128
#define NH 256
#define NK 12
#define INV_TEMP 10.0f
#define BT (NB*NT)   // 32768

// ---------------- device scratch (no allocations allowed) ---------------------
__device__ float g_Wf[NF*NP];                       // fused encoder weight 256x128
__device__ float g_bz[NP];                          // fused encoder bias
__device__ float g_gi[(size_t)BT*3*NH];             // gi      (b,t,768)
__device__ __align__(16) __nv_bfloat16 g_zp[(size_t)BT*256];       // z split [hi|lo]
__device__ __align__(16) __nv_bfloat16 g_cp[(size_t)BT*512];       // c split per-half [hi|lo]
__device__ __align__(16) __nv_bfloat16 g_wps[(size_t)2*1536*256];  // Wp split n-major
__device__ __align__(16) __nv_bfloat16 g_wis[(size_t)768*256];     // Wi split n-major

// ---------------- helpers -----------------------------------------------------
__device__ __forceinline__ unsigned smem_u32(const void* p){
    unsigned r;
    asm("{ .reg .u64 t; cvta.to.shared.u64 t, %1; cvt.u32.u64 %0, t; }" : "=r"(r) : "l"(p));
    return r;
}
__device__ __forceinline__ void cp_async16(uint32_t saddr, const void* gptr, uint32_t srcsz){
    asm volatile("cp.async.cg.shared.global [%0], [%1], 16, %2;"
                 :: "r"(saddr), "l"(gptr), "r"(srcsz));
}
#define CP_COMMIT() asm volatile("cp.async.commit_group;" ::: "memory")
#define CP_WAIT0()  asm volatile("cp.async.wait_group 0;" ::: "memory")

__device__ __forceinline__ uint32_t pack2bf(__nv_bfloat16 a, __nv_bfloat16 b){
    __nv_bfloat162 t; t.x = a; t.y = b;
    return *reinterpret_cast<uint32_t*>(&t);
}

// ---------------- prep kernel: repack Wi/Wp + Wf gemm + bz (+loss zero) -------
// blocks [0,960): repack; block 960: bz; blocks 961,962: Wf gemm tiles.
#define PREP_REPACK_BLOCKS 960

__global__ void __launch_bounds__(512) prep_kernel(
    const float* __restrict__ Wi, __nv_bfloat16* __restrict__ wis,
    const float* __restrict__ Wp, __nv_bfloat16* __restrict__ wps,
    const float* __restrict__ b_enc, const float* __restrict__ W_proj,
    const float* __restrict__ b_proj, float* __restrict__ bz,
    float* __restrict__ out,
    const float* __restrict__ W_enc, float* __restrict__ Wf)
{
    const int bid = blockIdx.x;
    const int tid = threadIdx.x;

    if (bid < PREP_REPACK_BLOCKS){
        int idx = bid*512 + tid;
        if (idx < 128*768){
            int n = idx % 768;
            int k = idx / 768;
            float v = Wi[idx];
            __nv_bfloat16 hi = __float2bfloat16(v);
            wis[(size_t)n*256 + k]       = hi;
            wis[(size_t)n*256 + 128 + k] = __float2bfloat16(v - __bfloat162float(hi));
            return;
        }
        idx -= 128*768;
        if (idx >= NK*NH*NP) return;
        int p = idx & 127;
        int h = (idx >> 7) & 255;
        int k = idx >> 15;
        float v = Wp[idx];
        __nv_bfloat16 hi = __float2bfloat16(v);
        __nv_bfloat16 lo = __float2bfloat16(v - __bfloat162float(hi));
        int n = k*128 + p;
        int khalf = h >> 7, kr = h & 127;
        size_t base = ((size_t)khalf*1536 + n)*256;
        wps[base + kr]       = hi;
        wps[base + 128 + kr] = lo;
        return;
    }

    if (bid == PREP_REPACK_BLOCKS){
        if (tid == 0) *out = 0.f;
        if (tid < 128){
            float s = b_proj[tid];
            for (int e = 0; e < NF; e++) s += b_enc[e] * W_proj[e*NP + tid];
            bz[tid] = s;
        }
        return;
    }

    // ---- Wf gemm tile: Wf = W_enc(256x256) @ W_proj(256x128), m0 per block ----
    __shared__ float As[16][128];
    __shared__ float Bs[16][128];
    const int m0 = (bid - PREP_REPACK_BLOCKS - 1) * 128;
    const int tx = tid & 15, ty = (tid >> 4) & 15;
    float acc[8][8];
#pragma unroll
    for (int i=0;i<8;i++)
#pragma unroll
        for (int j=0;j<8;j++) acc[i][j] = 0.f;

    for (int k0 = 0; k0 < NF; k0 += 16){
        {   // A tile: 128x16 = 512 float4 (one per thread)
            int r  = tid >> 2;
            int c4 = (tid & 3) << 2;
            const float4 v = *reinterpret_cast<const float4*>(W_enc + (size_t)(m0+r)*NF + k0 + c4);
            As[c4+0][r]=v.x; As[c4+1][r]=v.y; As[c4+2][r]=v.z; As[c4+3][r]=v.w;
        }
        {   // B tile: 16x128 = 512 float4
            int r  = tid >> 5;
            int c4 = (tid & 31) << 2;
            *reinterpret_cast<float4*>(&Bs[r][c4]) =
                *reinterpret_cast<const float4*>(W_proj + (size_t)(k0+r)*NP + c4);
        }
        __syncthreads();
        if (tid < 256){
#pragma unroll
            for (int k = 0; k < 16; k++){
                float a[8], b[8];
                *reinterpret_cast<float4*>(&a[0]) = *reinterpret_cast<float4*>(&As[k][ty*4]);
                *reinterpret_cast<float4*>(&a[4]) = *reinterpret_cast<float4*>(&As[k][ty*4+64]);
                *reinterpret_cast<float4*>(&b[0]) = *reinterpret_cast<float4*>(&Bs[k][tx*4]);
                *reinterpret_cast<float4*>(&b[4]) = *reinterpret_cast<float4*>(&Bs[k][tx*4+64]);
#pragma unroll
                for (int i=0;i<8;i++)
#pragma unroll
                    for (int j=0;j<8;j++) acc[i][j] += a[i]*b[j];
            }
        }
        __syncthreads();
    }
    if (tid < 256){
#pragma unroll
        for (int i=0;i<8;i++){
            int m = m0 + ty*4 + (i&3) + ((i>>2)<<6);
#pragma unroll
            for (int jg=0;jg<2;jg++){
                int n = tx*4 + jg*64;
                float4 v;
                v.x = acc[i][jg*4+0]; v.y = acc[i][jg*4+1];
                v.z = acc[i][jg*4+2]; v.w = acc[i][jg*4+3];
                *reinterpret_cast<float4*>(Wf + (size_t)m*NP + n) = v;
            }
        }
    }
}

// ---------------- z GEMM writing split-bf16 zp directly ------------------------
__global__ void __launch_bounds__(256) zgemm_pack_kernel(
    const float* __restrict__ A, const float* __restrict__ Bm,
    const float* __restrict__ bias, __nv_bfloat16* __restrict__ zp)
{
    __shared__ float As[16][128];
    __shared__ float Bs[16][128];
    const int tid = threadIdx.x;
    const int m0 = blockIdx.y * 128;
    const int tx = tid & 15, ty = tid >> 4;
    float acc[8][8];
#pragma unroll
    for (int i=0;i<8;i++)
#pragma unroll
        for (int j=0;j<8;j++) acc[i][j] = 0.f;

    for (int k0 = 0; k0 < NF; k0 += 16) {
#pragma unroll
        for (int it = 0; it < 2; it++) {
            int idx = tid + it*256;
            int r  = idx >> 2;
            int c4 = (idx & 3) << 2;
            const float4 v = *reinterpret_cast<const float4*>(A + (size_t)(m0+r)*NF + k0 + c4);
            As[c4+0][r]=v.x; As[c4+1][r]=v.y; As[c4+2][r]=v.z; As[c4+3][r]=v.w;
        }
#pragma unroll
        for (int it = 0; it < 2; it++) {
            int idx = tid + it*256;
            int r  = idx >> 5;
            int c4 = (idx & 31) << 2;
            *reinterpret_cast<float4*>(&Bs[r][c4]) =
                *reinterpret_cast<const float4*>(Bm + (size_t)(k0+r)*NP + c4);
        }
        __syncthreads();
#pragma unroll
        for (int k = 0; k < 16; k++) {
            float a[8], b[8];
            *reinterpret_cast<float4*>(&a[0]) = *reinterpret_cast<float4*>(&As[k][ty*4]);
            *reinterpret_cast<float4*>(&a[4]) = *reinterpret_cast<float4*>(&As[k][ty*4+64]);
            *reinterpret_cast<float4*>(&b[0]) = *reinterpret_cast<float4*>(&Bs[k][tx*4]);
            *reinterpret_cast<float4*>(&b[4]) = *reinterpret_cast<float4*>(&Bs[k][tx*4+64]);
#pragma unroll
            for (int i=0;i<8;i++)
#pragma unroll
                for (int j=0;j<8;j++) acc[i][j] += a[i]*b[j];
        }
        __syncthreads();
    }
#pragma unroll
    for (int i=0;i<8;i++){
        int m = m0 + ty*4 + (i&3) + ((i>>2)<<6);
        __nv_bfloat16* rowp = zp + (size_t)m*256;
#pragma unroll
        for (int jg=0;jg<2;jg++){
            int n = tx*4 + jg*64;
            const float4 bv = *reinterpret_cast<const float4*>(bias + n);
            float v0 = acc[i][jg*4+0] + bv.x;
            float v1 = acc[i][jg*4+1] + bv.y;
            float v2 = acc[i][jg*4+2] + bv.z;
            float v3 = acc[i][jg*4+3] + bv.w;
            __nv_bfloat16 h0=__float2bfloat16(v0), h1=__float2bfloat16(v1);
            __nv_bfloat16 h2=__float2bfloat16(v2), h3=__float2bfloat16(v3);
            uint2 hv, lv;
            hv.x = pack2bf(h0,h1); hv.y = pack2bf(h2,h3);
            lv.x = pack2bf(__float2bfloat16(v0-__bfloat162float(h0)),
                           __float2bfloat16(v1-__bfloat162float(h1)));
            lv.y = pack2bf(__float2bfloat16(v2-__bfloat162float(h2)),
                           __float2bfloat16(v3-__bfloat162float(h3)));
            *reinterpret_cast<uint2*>(rowp + n)       = hv;
            *reinterpret_cast<uint2*>(rowp + 128 + n) = lv;
        }
    }
}

// ---------------- mma primitives ----------------------------------------------
__device__ __forceinline__ void ldmatrix_x4(uint32_t& r0, uint32_t& r1, uint32_t& r2, uint32_t& r3,
                                            uint32_t addr){
    asm volatile("ldmatrix.sync.aligned.m8n8.x4.shared.b16 {%0,%1,%2,%3}, [%4];"
        : "=r"(r0), "=r"(r1), "=r"(r2), "=r"(r3) : "r"(addr));
}
__device__ __forceinline__ void mma16816(float* d, const uint32_t* a, uint32_t b0, uint32_t b1){
    asm volatile("mma.sync.aligned.m16n8k16.row.col.f32.bf16.bf16.f32 "
        "{%0,%1,%2,%3}, {%4,%5,%6,%7}, {%8,%9}, {%0,%1,%2,%3};"
        : "+f"(d[0]), "+f"(d[1]), "+f"(d[2]), "+f"(d[3])
        : "r"(a[0]), "r"(a[1]), "r"(a[2]), "r"(a[3]), "r"(b0), "r"(b1));
}

// ---------------- gi GEMM via mma.sync (3-term split bf16) --------------------
#define PRS 264
#define GI_SMEM_BYTES (2*128*PRS*2)

__global__ void __launch_bounds__(256) gi_mma_kernel(
    const __nv_bfloat16* __restrict__ zp, const __nv_bfloat16* __restrict__ wis,
    const float* __restrict__ bi, float* __restrict__ gi)
{
    extern __shared__ __align__(16) char gsm[];
    __nv_bfloat16* SA = reinterpret_cast<__nv_bfloat16*>(gsm);
    __nv_bfloat16* SB = SA + 128*PRS;
    const uint32_t SAb = smem_u32(SA);
    const uint32_t SBb = smem_u32(SB);

    const int tid  = threadIdx.x;
    const int warp = tid >> 5;
    const int lane = tid & 31;
    const int n0   = blockIdx.x * 128;
    const int m0   = blockIdx.y * 128;

    for (int it = 0; it < 16; it++){
        int idx = tid + it*256;
        int r = idx >> 5, u = idx & 31;
        *reinterpret_cast<uint4*>(SA + r*PRS + u*8) =
            *reinterpret_cast<const uint4*>(zp + (size_t)(m0 + r)*256 + u*8);
        *reinterpret_cast<uint4*>(SB + r*PRS + u*8) =
            *reinterpret_cast<const uint4*>(wis + (size_t)(n0 + r)*256 + u*8);
    }
    __syncthreads();

    const uint32_t lrow = (lane & 7) + ((lane >> 3) & 1)*8;
    const uint32_t lcol = (lane >> 4)*8;
    const int mw = warp * 16;

    uint32_t afr[16][4];
#pragma unroll
    for (int kc = 0; kc < 16; kc++){
        uint32_t addr = SAb + ((mw + lrow)*PRS + kc*16 + lcol)*2;
        ldmatrix_x4(afr[kc][0], afr[kc][1], afr[kc][2], afr[kc][3], addr);
    }

    float acc[16][4];
#pragma unroll
    for (int nf = 0; nf < 16; nf++)
#pragma unroll
        for (int i = 0; i < 4; i++) acc[nf][i] = 0.f;

#pragma unroll
    for (int kc = 0; kc < 16; kc++){
#pragma unroll
        for (int nf2 = 0; nf2 < 8; nf2++){
            uint32_t r0,r1,r2,r3;
            uint32_t addr = SBb + ((nf2*16 + lrow)*PRS + kc*16 + lcol)*2;
            ldmatrix_x4(r0, r1, r2, r3, addr);
            if (kc < 8){
                mma16816(acc[nf2*2+0], afr[kc],   r0, r2);
                mma16816(acc[nf2*2+1], afr[kc],   r1, r3);
                mma16816(acc[nf2*2+0], afr[kc+8], r0, r2);
                mma16816(acc[nf2*2+1], afr[kc+8], r1, r3);
            } else {
                mma16816(acc[nf2*2+0], afr[kc-8], r0, r2);
                mma16816(acc[nf2*2+1], afr[kc-8], r1, r3);
            }
        }
    }

    const int r0g = m0 + mw + (lane >> 2);
#pragma unroll
    for (int nf = 0; nf < 16; nf++){
        int c0 = n0 + nf*8 + (lane & 3)*2;
        float b0 = bi[c0], b1 = bi[c0+1];
#pragma unroll
        for (int rr = 0; rr < 2; rr++){
            float2 v;
            v.x = acc[nf][rr*2+0] + b0;
            v.y = acc[nf][rr*2+1] + b1;
            *reinterpret_cast<float2*>(gi + (size_t)(r0g + rr*8)*768 + c0) = v;
        }
    }
}

// ---------------- GRU scan (proven layout; hoisted mapa addresses) ------------
__device__ __forceinline__ void cluster_sync_all(){
    asm volatile("barrier.cluster.arrive.aligned;" ::: "memory");
    asm volatile("barrier.cluster.wait.aligned;"   ::: "memory");
}

#define GRU_SMEM_FLOATS 28192
#define GRU_SMEM_BYTES  (GRU_SMEM_FLOATS*4)

__global__ void __launch_bounds__(384) __cluster_dims__(8,1,1)
gru_kernel(const float* __restrict__ gi, const float* __restrict__ Wh,
           const float* __restrict__ bhn, __nv_bfloat16* __restrict__ cp_out)
{
    extern __shared__ float sm[];
    float* Whs   = sm;            // [256][96]
    float* h2    = sm + 24576;    // [2][256][4]
    float* part  = sm + 26624;    // [q*4+b][96]
    float* bhn_s = sm + 28160;    // [32]

    const int tid  = threadIdx.x;
    const int rank = blockIdx.x & 7;
    const int b0   = (blockIdx.x >> 3) * 4;
    const int u0   = rank * 32;

    for (int i = tid; i < 256*96; i += 384){
        int u = i / 96, c = i % 96;
        int gcol = (c >> 5)*256 + u0 + (c & 31);
        Whs[i] = Wh[u*768 + gcol];
    }
    for (int i = tid; i < 2048; i += 384) h2[i] = 0.f;
    if (tid < 32) bhn_s[tid] = bhn[u0 + tid];
    __syncthreads();
    cluster_sync_all();

    const int c  = tid % 96;
    const int q  = tid / 96;
    const int b3 = tid >> 5;
    const int ul = tid & 31;

    // hoisted remote store addresses (loop-invariant; 2 buffers x 8 ranks)
    unsigned ra0[8], ra1[8];
    if (tid < 128){
        unsigned l0 = smem_u32(h2 + (u0+ul)*4 + b3);
        unsigned l1 = l0 + 4096;
#pragma unroll
        for (int r8 = 0; r8 < 8; r8++){
            asm("mapa.shared::cluster.u32 %0, %1, %2;" : "=r"(ra0[r8]) : "r"(l0), "r"(r8));
            asm("mapa.shared::cluster.u32 %0, %1, %2;" : "=r"(ra1[r8]) : "r"(l1), "r"(r8));
        }
    }

    int cur = 0;
    for (int t = 0; t < NT; t++){
        float gir=0.f, giz=0.f, gin=0.f;
        if (tid < 128){
            const float* gp = gi + ((size_t)(b0+b3)*NT + t)*768;
            gir = gp[u0+ul]; giz = gp[256+u0+ul]; gin = gp[512+u0+ul];
        }
        {
            const float* hb = h2 + cur*1024;
            float a0=0.f,a1=0.f,a2=0.f,a3=0.f;
            const int ub = q*64;
#pragma unroll 8
            for (int uu = 0; uu < 64; uu++){
                int u = ub + uu;
                float w = Whs[u*96 + c];
                float4 h4 = *reinterpret_cast<const float4*>(hb + u*4);
                a0 += w*h4.x; a1 += w*h4.y; a2 += w*h4.z; a3 += w*h4.w;
            }
            part[(q*4+0)*96 + c] = a0;
            part[(q*4+1)*96 + c] = a1;
            part[(q*4+2)*96 + c] = a2;
            part[(q*4+3)*96 + c] = a3;
        }
        __syncthreads();

        int nxt = cur ^ 1;
        if (tid < 128){
            float hr = part[(0*4+b3)*96 + ul]      + part[(1*4+b3)*96 + ul]
                     + part[(2*4+b3)*96 + ul]      + part[(3*4+b3)*96 + ul];
            float hz = part[(0*4+b3)*96 + 32 + ul] + part[(1*4+b3)*96 + 32 + ul]
                     + part[(2*4+b3)*96 + 32 + ul] + part[(3*4+b3)*96 + 32 + ul];
            float hn = part[(0*4+b3)*96 + 64 + ul] + part[(1*4+b3)*96 + 64 + ul]
                     + part[(2*4+b3)*96 + 64 + ul] + part[(3*4+b3)*96 + 64 + ul];
            float r  = 1.f/(1.f + expf(-(gir + hr)));
            float zz = 1.f/(1.f + expf(-(giz + hz)));
            float n  = tanhf(gin + r*(hn + bhn_s[ul]));
            float hp = h2[cur*1024 + (u0+ul)*4 + b3];
            float hnew = (1.f - zz)*n + zz*hp;
            int g = u0 + ul;
            size_t base = (((size_t)(b0+b3)*NT + t))*512 + (size_t)(g>>7)*256 + (g & 127);
            __nv_bfloat16 hh = __float2bfloat16(hnew);
            cp_out[base]       = hh;
            cp_out[base + 128] = __float2bfloat16(hnew - __bfloat162float(hh));
#pragma unroll
            for (int r8 = 0; r8 < 8; r8++){
                unsigned ad = nxt ? ra1[r8] : ra0[r8];
                asm volatile("st.shared::cluster.f32 [%0], %1;" :: "r"(ad), "f"(hnew) : "memory");
            }
        }
        cluster_sync_all();
        cur = nxt;
    }
}

// ---------------- fused pred + streaming-softmax loss --------------------------
#define LOSS_RS 264
#define ZT_ROWS 64
#define LOSS_SMEM_BYTES (128*LOSS_RS*2)

__global__ void __launch_bounds__(256,2) loss_fused_kernel(
    const __nv_bfloat16* __restrict__ cp, const __nv_bfloat16* __restrict__ wps,
    const float* __restrict__ bp, const __nv_bfloat16* __restrict__ zp,
    float* __restrict__ out)
{
    extern __shared__ __align__(16) char lsm[];
    __nv_bfloat16* Sbuf = reinterpret_cast<__nv_bfloat16*>(lsm);
    const uint32_t Sb = smem_u32(Sbuf);
    const uint32_t SZb[2] = { Sb, Sb + ZT_ROWS*LOSS_RS*2 };
    __shared__ float wsum[16];

    const int tid  = threadIdx.x;
    const int warp = tid >> 5;
    const int lane = tid & 31;
    const int b    = blockIdx.y;
    const int k    = blockIdx.z + 1;
    const int t0   = blockIdx.x * 128;
    const int Tm   = NT - k;
    const int kk   = k - 1;
    const int mg   = b*NT + t0;

    const uint32_t lrow = (lane & 7) + ((lane >> 3) & 1)*8;
    const uint32_t lcol = (lane >> 4)*8;
    const int mw = warp * 16;

    // ================= Phase 1: pred A-tile (A from global, Wp in smem) =======
    float acc[16][4];
#pragma unroll
    for (int nf = 0; nf < 16; nf++)
#pragma unroll
        for (int i = 0; i < 4; i++) acc[nf][i] = 0.f;

    for (int khalf = 0; khalf < 2; khalf++){
        for (int it = 0; it < 16; it++){
            int idx = tid + it*256;
            int r = idx >> 5, u = idx & 31;
            *reinterpret_cast<uint4*>(Sbuf + r*LOSS_RS + u*8) =
                *reinterpret_cast<const uint4*>(wps + ((size_t)khalf*1536 + kk*128 + r)*256 + u*8);
        }
        __syncthreads();

        const char* cb = reinterpret_cast<const char*>(
            cp + (size_t)(mg + mw + (lane >> 2))*512 + khalf*256 + (lane & 3)*2);
        const size_t row8 = 8*512*2;

#pragma unroll
        for (int kc = 0; kc < 8; kc++){
            uint32_t ahi[4], alo[4];
            const char* ph = cb + (kc*16)*2;
            const char* pl = cb + ((kc+8)*16)*2;
            ahi[0] = *reinterpret_cast<const uint32_t*>(ph);
            ahi[1] = *reinterpret_cast<const uint32_t*>(ph + row8);
            ahi[2] = *reinterpret_cast<const uint32_t*>(ph + 16);
            ahi[3] = *reinterpret_cast<const uint32_t*>(ph + row8 + 16);
            alo[0] = *reinterpret_cast<const uint32_t*>(pl);
            alo[1] = *reinterpret_cast<const uint32_t*>(pl + row8);
            alo[2] = *reinterpret_cast<const uint32_t*>(pl + 16);
            alo[3] = *reinterpret_cast<const uint32_t*>(pl + row8 + 16);
#pragma unroll
            for (int nf2 = 0; nf2 < 8; nf2++){
                uint32_t r0,r1,r2,r3;
                uint32_t addr = Sb + ((nf2*16 + lrow)*LOSS_RS + kc*16 + lcol)*2;
                ldmatrix_x4(r0, r1, r2, r3, addr);
                mma16816(acc[nf2*2+0], ahi, r0, r2);
                mma16816(acc[nf2*2+1], ahi, r1, r3);
                mma16816(acc[nf2*2+0], alo, r0, r2);
                mma16816(acc[nf2*2+1], alo, r1, r3);
                addr = Sb + ((nf2*16 + lrow)*LOSS_RS + (kc+8)*16 + lcol)*2;
                ldmatrix_x4(r0, r1, r2, r3, addr);
                mma16816(acc[nf2*2+0], ahi, r0, r2);
                mma16816(acc[nf2*2+1], ahi, r1, r3);
            }
        }
        __syncthreads();
    }

    // ---- issue Z tile 0 prefetch (64 rows) ----
    for (int it = 0; it < 8; it++){
        int idx = tid + it*256;
        int j = idx >> 5, u = idx & 31;
        int jr = k + j;
        uint32_t ok = (jr < NT) ? 16u : 0u;
        int jc = jr < NT ? jr : NT-1;
        cp_async16(SZb[0] + (uint32_t)(j*LOSS_RS + u*8)*2,
                   zp + ((size_t)(b*NT) + jc)*256 + u*8, ok);
    }
    CP_COMMIT();

    // ---- build split-bf16 A-fragments in registers ----
    uint32_t afr[16][4];
    {
        const int ct2 = (lane & 3)*2;
#pragma unroll
        for (int nf = 0; nf < 16; nf++){
            float b0 = bp[kk*128 + nf*8 + ct2];
            float b1 = bp[kk*128 + nf*8 + ct2 + 1];
            acc[nf][0] = (acc[nf][0] + b0) * INV_TEMP;
            acc[nf][1] = (acc[nf][1] + b1) * INV_TEMP;
            acc[nf][2] = (acc[nf][2] + b0) * INV_TEMP;
            acc[nf][3] = (acc[nf][3] + b1) * INV_TEMP;
        }
#pragma unroll
        for (int kc = 0; kc < 8; kc++){
#pragma unroll
            for (int r2 = 0; r2 < 4; r2++){
                int nf = 2*kc + (r2 >> 1);
                int e0 = (r2 & 1)*2, e1 = e0 + 1;
                float v0 = acc[nf][e0], v1 = acc[nf][e1];
                __nv_bfloat16 h0 = __float2bfloat16(v0);
                __nv_bfloat16 h1 = __float2bfloat16(v1);
                afr[kc][r2]   = pack2bf(h0, h1);
                afr[kc+8][r2] = pack2bf(__float2bfloat16(v0 - __bfloat162float(h0)),
                                        __float2bfloat16(v1 - __bfloat162float(h1)));
            }
        }
    }

    // ================= Phase 2: streaming softmax (8 x 64-row tiles) ==========
    const int ra = t0 + mw + (lane >> 2);
    const bool rv0 = ra < Tm, rv1 = (ra + 8) < Tm;
    float mr[2] = {-1e30f, -1e30f};
    float sr[2] = {0.f, 0.f};
    float tot = 0.f;

    for (int jt = 0; jt < 8; jt++){
        const int j0 = jt * ZT_ROWS;
        CP_WAIT0();
        __syncthreads();
        if (jt < 7){
            const int jn = (jt+1) * ZT_ROWS;
            const uint32_t dst = SZb[(jt+1) & 1];
            for (int it = 0; it < 8; it++){
                int idx = tid + it*256;
                int j = idx >> 5, u = idx & 31;
                int jr = k + jn + j;
                uint32_t ok = (jr < NT) ? 16u : 0u;
                int jc = jr < NT ? jr : NT-1;
                cp_async16(dst + (uint32_t)(j*LOSS_RS + u*8)*2,
                           zp + ((size_t)(b*NT) + jc)*256 + u*8, ok);
            }
            CP_COMMIT();
        }
        const uint32_t Zb = SZb[jt & 1];

        float lac[8][4];
#pragma unroll
        for (int nf = 0; nf < 8; nf++)
#pragma unroll
            for (int i = 0; i < 4; i++) lac[nf][i] = 0.f;

#pragma unroll
        for (int kc = 0; kc < 16; kc++){
#pragma unroll
            for (int nf2 = 0; nf2 < 4; nf2++){
                uint32_t r0,r1,r2,r3;
                uint32_t addr = Zb + (uint32_t)((nf2*16 + lrow)*LOSS_RS + kc*16 + lcol)*2;
                ldmatrix_x4(r0, r1, r2, r3, addr);
                if (kc < 8){
                    mma16816(lac[nf2*2+0], afr[kc],   r0, r2);
                    mma16816(lac[nf2*2+1], afr[kc],   r1, r3);
                    mma16816(lac[nf2*2+0], afr[kc+8], r0, r2);
                    mma16816(lac[nf2*2+1], afr[kc+8], r1, r3);
                } else {
                    mma16816(lac[nf2*2+0], afr[kc-8], r0, r2);
                    mma16816(lac[nf2*2+1], afr[kc-8], r1, r3);
                }
            }
        }

        if (j0 + ZT_ROWS <= Tm){
            float tm[2] = {-1e30f, -1e30f};
#pragma unroll
            for (int nf = 0; nf < 8; nf++){
                tm[0] = fmaxf(tm[0], fmaxf(lac[nf][0], lac[nf][1]));
                tm[1] = fmaxf(tm[1], fmaxf(lac[nf][2], lac[nf][3]));
            }
#pragma unroll
            for (int o = 1; o <= 2; o <<= 1){
                tm[0] = fmaxf(tm[0], __shfl_xor_sync(0xFFFFFFFFu, tm[0], o));
                tm[1] = fmaxf(tm[1], __shfl_xor_sync(0xFFFFFFFFu, tm[1], o));
            }
#pragma unroll
            for (int rr = 0; rr < 2; rr++){
                float nm = fmaxf(mr[rr], tm[rr]);
                sr[rr] *= __expf(mr[rr] - nm);
                mr[rr] = nm;
            }
            float ls0 = 0.f, ls1 = 0.f, lt0 = 0.f, lt1 = 0.f;
#pragma unroll
            for (int nf = 0; nf < 8; nf++){
                ls0 += __expf(lac[nf][0] - mr[0]) + __expf(lac[nf][1] - mr[0]);
                ls1 += __expf(lac[nf][2] - mr[1]) + __expf(lac[nf][3] - mr[1]);
                lt0 += lac[nf][0] + lac[nf][1];
                lt1 += lac[nf][2] + lac[nf][3];
            }
            sr[0] += ls0; sr[1] += ls1;
            if (rv0) tot += lt0;
            if (rv1) tot += lt1;
        } else {
            const int cbase = j0 + (lane & 3)*2;
            float tm[2] = {-1e30f, -1e30f};
#pragma unroll
            for (int nf = 0; nf < 8; nf++){
                int c0 = cbase + nf*8;
                bool v0 = c0 < Tm, v1 = (c0+1) < Tm;
                if (v0){ tm[0] = fmaxf(tm[0], lac[nf][0]); tm[1] = fmaxf(tm[1], lac[nf][2]); }
                if (v1){ tm[0] = fmaxf(tm[0], lac[nf][1]); tm[1] = fmaxf(tm[1], lac[nf][3]); }
            }
#pragma unroll
            for (int o = 1; o <= 2; o <<= 1){
                tm[0] = fmaxf(tm[0], __shfl_xor_sync(0xFFFFFFFFu, tm[0], o));
                tm[1] = fmaxf(tm[1], __shfl_xor_sync(0xFFFFFFFFu, tm[1], o));
            }
            if (tm[0] > -1e29f){
#pragma unroll
                for (int rr = 0; rr < 2; rr++){
                    float nm = fmaxf(mr[rr], tm[rr]);
                    sr[rr] *= __expf(mr[rr] - nm);
                    mr[rr] = nm;
                }
                float ls0 = 0.f, ls1 = 0.f, lt0 = 0.f, lt1 = 0.f;
#pragma unroll
                for (int nf = 0; nf < 8; nf++){
                    int c0 = cbase + nf*8;
#pragma unroll
                    for (int h = 0; h < 2; h++){
                        if (c0 + h < Tm){
                            ls0 += __expf(lac[nf][h]   - mr[0]);
                            ls1 += __expf(lac[nf][2+h] - mr[1]);
                            lt0 += lac[nf][h]; lt1 += lac[nf][2+h];
                        }
                    }
                }
                sr[0] += ls0; sr[1] += ls1;
                if (rv0) tot += lt0;
                if (rv1) tot += lt1;
            }
        }
        __syncthreads();
    }

    // ---- finalize ----
#pragma unroll
    for (int o = 1; o <= 2; o <<= 1){
        sr[0] += __shfl_xor_sync(0xFFFFFFFFu, sr[0], o);
        sr[1] += __shfl_xor_sync(0xFFFFFFFFu, sr[1], o);
    }
    float lse = 0.f;
    if ((lane & 3) == 0){
        if (rv0) lse += mr[0] + __logf(sr[0]);
        if (rv1) lse += mr[1] + __logf(sr[1]);
    }
#pragma unroll
    for (int o = 16; o; o >>= 1){
        lse += __shfl_xor_sync(0xFFFFFFFFu, lse, o);
        tot += __shfl_xor_sync(0xFFFFFFFFu, tot, o);
    }
    if (lane == 0){ wsum[warp] = lse; wsum[8+warp] = tot; }
    __syncthreads();
    if (tid == 0){
        float L = 0.f, T = 0.f;
#pragma unroll
        for (int w = 0; w < 8; w++){ L += wsum[w]; T += wsum[8+w]; }
        float inv = 1.0f / ((float)NB * (float)Tm * (float)NK);
        atomicAdd(out, L*inv - T*(inv/(float)Tm));
    }
}

// ---------------- launch ------------------------------------------------------
extern "C" void kernel_launch(void* const* d_in, const int* in_sizes, int n_in,
                              void* d_out, int out_size)
{
    const float* x_seq  = (const float*)d_in[0];
    const float* W_enc  = (const float*)d_in[1];
    const float* b_enc  = (const float*)d_in[2];
    const float* W_proj = (const float*)d_in[3];
    const float* b_proj = (const float*)d_in[4];
    const float* Wi     = (const float*)d_in[5];
    const float* bi     = (const float*)d_in[6];
    const float* Wh     = (const float*)d_in[7];
    const float* bhn    = (const float*)d_in[8];
    const float* Wp     = (const float*)d_in[9];
    const float* bp     = (const float*)d_in[10];
    float* out = (float*)d_out;

    float *Wf, *bz, *gibuf;
    __nv_bfloat16 *zpb, *cpb, *wpsb, *wisb;
    cudaGetSymbolAddress((void**)&Wf,    g_Wf);
    cudaGetSymbolAddress((void**)&bz,    g_bz);
    cudaGetSymbolAddress((void**)&gibuf, g_gi);
    cudaGetSymbolAddress((void**)&zpb,   g_zp);
    cudaGetSymbolAddress((void**)&cpb,   g_cp);
    cudaGetSymbolAddress((void**)&wpsb,  g_wps);
    cudaGetSymbolAddress((void**)&wisb,  g_wis);

    cudaFuncSetAttribute(gru_kernel,        cudaFuncAttributeMaxDynamicSharedMemorySize, GRU_SMEM_BYTES);
    cudaFuncSetAttribute(loss_fused_kernel, cudaFuncAttributeMaxDynamicSharedMemorySize, LOSS_SMEM_BYTES);
    cudaFuncSetAttribute(gi_mma_kernel,     cudaFuncAttributeMaxDynamicSharedMemorySize, GI_SMEM_BYTES);

    // 1: prep (repack Wi/Wp + Wf gemm + bz + loss zero)
    prep_kernel<<<PREP_REPACK_BLOCKS + 3, 512>>>(
        Wi, wisb, Wp, wpsb, b_enc, W_proj, b_proj, bz, out, W_enc, Wf);
    // 2: zp = split(x @ Wf + bz)
    zgemm_pack_kernel<<<dim3(1,256), 256>>>(x_seq, Wf, bz, zpb);
    // 3: gi = z @ Wi + bi  (tensor path)
    gi_mma_kernel<<<dim3(6,256), 256, GI_SMEM_BYTES>>>(zpb, wisb, bi, gibuf);
    // 4: GRU scan (persistent, clustered) — lands in the ncu capture slot
    gru_kernel<<<128, 384, GRU_SMEM_BYTES>>>(gibuf, Wh, bhn, cpb);
    // 5: fused pred + streaming-softmax loss
    loss_fused_kernel<<<dim3(4,64,12), 256, LOSS_SMEM_BYTES>>>(cpb, wpsb, bp, zpb, out);
}

// round 17
// speedup vs baseline: 1.0336x; 1.0336x over previous
#include <cuda_runtime.h>
#include <cuda_bf16.h>
#include <cstdint>
#include <math.h>

// Problem constants
#define NB 64
#define NT 512
#define NF 256
#define NP 128
#define NH 256
#define NK 12
#define INV_TEMP 10.0f
#define BT (NB*NT)   // 32768

// ---------------- device scratch (no allocations allowed) ---------------------
__device__ float g_Wf[NF*NP];                       // fused encoder weight 256x128
__device__ float g_bz[NP];                          // fused encoder bias
__device__ float g_gi[(size_t)BT*3*NH];             // gi      (b,t,768)
__device__ __align__(16) float g_z32[(size_t)BT*128];              // z tf32-rounded fp32
__device__ __align__(16) __nv_bfloat16 g_zp[(size_t)BT*256];       // z split [hi|lo] (gi)
__device__ __align__(16) __nv_bfloat16 g_cp[(size_t)BT*512];       // c split per-half [hi|lo]
__device__ __align__(16) __nv_bfloat16 g_wps[(size_t)2*1536*256];  // Wp split n-major
__device__ __align__(16) __nv_bfloat16 g_wis[(size_t)768*256];     // Wi split n-major

// ---------------- helpers -----------------------------------------------------
__device__ __forceinline__ unsigned smem_u32(const void* p){
    unsigned r;
    asm("{ .reg .u64 t; cvta.to.shared.u64 t, %1; cvt.u32.u64 %0, t; }" : "=r"(r) : "l"(p));
    return r;
}
__device__ __forceinline__ void cp_async16(uint32_t saddr, const void* gptr, uint32_t srcsz){
    asm volatile("cp.async.cg.shared.global [%0], [%1], 16, %2;"
                 :: "r"(saddr), "l"(gptr), "r"(srcsz));
}
#define CP_COMMIT() asm volatile("cp.async.commit_group;" ::: "memory")
#define CP_WAIT0()  asm volatile("cp.async.wait_group 0;" ::: "memory")

__device__ __forceinline__ uint32_t pack2bf(__nv_bfloat16 a, __nv_bfloat16 b){
    __nv_bfloat162 t; t.x = a; t.y = b;
    return *reinterpret_cast<uint32_t*>(&t);
}
__device__ __forceinline__ uint32_t f2tf32(float f){
    uint32_t r;
    asm("cvt.rna.tf32.f32 %0, %1;" : "=r"(r) : "f"(f));
    return r;
}
__device__ __forceinline__ float tf32r(float f){   // tf32-rounded value as float
    uint32_t r = f2tf32(f);
    return __uint_as_float(r);
}

// ---------------- prep kernel: repack Wi/Wp + Wf gemm + bz (+loss zero) -------
#define PREP_REPACK_BLOCKS 960

__global__ void __launch_bounds__(512) prep_kernel(
    const float* __restrict__ Wi, __nv_bfloat16* __restrict__ wis,
    const float* __restrict__ Wp, __nv_bfloat16* __restrict__ wps,
    const float* __restrict__ b_enc, const float* __restrict__ W_proj,
    const float* __restrict__ b_proj, float* __restrict__ bz,
    float* __restrict__ out,
    const float* __restrict__ W_enc, float* __restrict__ Wf)
{
    const int bid = blockIdx.x;
    const int tid = threadIdx.x;

    if (bid < PREP_REPACK_BLOCKS){
        int idx = bid*512 + tid;
        if (idx < 128*768){
            int n = idx % 768;
            int k = idx / 768;
            float v = Wi[idx];
            __nv_bfloat16 hi = __float2bfloat16(v);
            wis[(size_t)n*256 + k]       = hi;
            wis[(size_t)n*256 + 128 + k] = __float2bfloat16(v - __bfloat162float(hi));
            return;
        }
        idx -= 128*768;
        if (idx >= NK*NH*NP) return;
        int p = idx & 127;
        int h = (idx >> 7) & 255;
        int k = idx >> 15;
        float v = Wp[idx];
        __nv_bfloat16 hi = __float2bfloat16(v);
        __nv_bfloat16 lo = __float2bfloat16(v - __bfloat162float(hi));
        int n = k*128 + p;
        int khalf = h >> 7, kr = h & 127;
        size_t base = ((size_t)khalf*1536 + n)*256;
        wps[base + kr]       = hi;
        wps[base + 128 + kr] = lo;
        return;
    }

    if (bid == PREP_REPACK_BLOCKS){
        if (tid == 0) *out = 0.f;
        if (tid < 128){
            float s = b_proj[tid];
            for (int e = 0; e < NF; e++) s += b_enc[e] * W_proj[e*NP + tid];
            bz[tid] = s;
        }
        return;
    }

    // ---- Wf gemm tile ----
    __shared__ float As[16][128];
    __shared__ float Bs[16][128];
    const int m0 = (bid - PREP_REPACK_BLOCKS - 1) * 128;
    const int tx = tid & 15, ty = (tid >> 4) & 15;
    float acc[8][8];
#pragma unroll
    for (int i=0;i<8;i++)
#pragma unroll
        for (int j=0;j<8;j++) acc[i][j] = 0.f;

    for (int k0 = 0; k0 < NF; k0 += 16){
        {
            int r  = tid >> 2;
            int c4 = (tid & 3) << 2;
            const float4 v = *reinterpret_cast<const float4*>(W_enc + (size_t)(m0+r)*NF + k0 + c4);
            As[c4+0][r]=v.x; As[c4+1][r]=v.y; As[c4+2][r]=v.z; As[c4+3][r]=v.w;
        }
        {
            int r  = tid >> 5;
            int c4 = (tid & 31) << 2;
            *reinterpret_cast<float4*>(&Bs[r][c4]) =
                *reinterpret_cast<const float4*>(W_proj + (size_t)(k0+r)*NP + c4);
        }
        __syncthreads();
        if (tid < 256){
#pragma unroll
            for (int k = 0; k < 16; k++){
                float a[8], b[8];
                *reinterpret_cast<float4*>(&a[0]) = *reinterpret_cast<float4*>(&As[k][ty*4]);
                *reinterpret_cast<float4*>(&a[4]) = *reinterpret_cast<float4*>(&As[k][ty*4+64]);
                *reinterpret_cast<float4*>(&b[0]) = *reinterpret_cast<float4*>(&Bs[k][tx*4]);
                *reinterpret_cast<float4*>(&b[4]) = *reinterpret_cast<float4*>(&Bs[k][tx*4+64]);
#pragma unroll
                for (int i=0;i<8;i++)
#pragma unroll
                    for (int j=0;j<8;j++) acc[i][j] += a[i]*b[j];
            }
        }
        __syncthreads();
    }
    if (tid < 256){
#pragma unroll
        for (int i=0;i<8;i++){
            int m = m0 + ty*4 + (i&3) + ((i>>2)<<6);
#pragma unroll
            for (int jg=0;jg<2;jg++){
                int n = tx*4 + jg*64;
                float4 v;
                v.x = acc[i][jg*4+0]; v.y = acc[i][jg*4+1];
                v.z = acc[i][jg*4+2]; v.w = acc[i][jg*4+3];
                *reinterpret_cast<float4*>(Wf + (size_t)m*NP + n) = v;
            }
        }
    }
}

// ---------------- z GEMM writing split-bf16 zp + tf32-rounded z32 --------------
__global__ void __launch_bounds__(256) zgemm_pack_kernel(
    const float* __restrict__ A, const float* __restrict__ Bm,
    const float* __restrict__ bias, __nv_bfloat16* __restrict__ zp,
    float* __restrict__ z32)
{
    __shared__ float As[16][128];
    __shared__ float Bs[16][128];
    const int tid = threadIdx.x;
    const int m0 = blockIdx.y * 128;
    const int tx = tid & 15, ty = tid >> 4;
    float acc[8][8];
#pragma unroll
    for (int i=0;i<8;i++)
#pragma unroll
        for (int j=0;j<8;j++) acc[i][j] = 0.f;

    for (int k0 = 0; k0 < NF; k0 += 16) {
#pragma unroll
        for (int it = 0; it < 2; it++) {
            int idx = tid + it*256;
            int r  = idx >> 2;
            int c4 = (idx & 3) << 2;
            const float4 v = *reinterpret_cast<const float4*>(A + (size_t)(m0+r)*NF + k0 + c4);
            As[c4+0][r]=v.x; As[c4+1][r]=v.y; As[c4+2][r]=v.z; As[c4+3][r]=v.w;
        }
#pragma unroll
        for (int it = 0; it < 2; it++) {
            int idx = tid + it*256;
            int r  = idx >> 5;
            int c4 = (idx & 31) << 2;
            *reinterpret_cast<float4*>(&Bs[r][c4]) =
                *reinterpret_cast<const float4*>(Bm + (size_t)(k0+r)*NP + c4);
        }
        __syncthreads();
#pragma unroll
        for (int k = 0; k < 16; k++) {
            float a[8], b[8];
            *reinterpret_cast<float4*>(&a[0]) = *reinterpret_cast<float4*>(&As[k][ty*4]);
            *reinterpret_cast<float4*>(&a[4]) = *reinterpret_cast<float4*>(&As[k][ty*4+64]);
            *reinterpret_cast<float4*>(&b[0]) = *reinterpret_cast<float4*>(&Bs[k][tx*4]);
            *reinterpret_cast<float4*>(&b[4]) = *reinterpret_cast<float4*>(&Bs[k][tx*4+64]);
#pragma unroll
            for (int i=0;i<8;i++)
#pragma unroll
                for (int j=0;j<8;j++) acc[i][j] += a[i]*b[j];
        }
        __syncthreads();
    }
#pragma unroll
    for (int i=0;i<8;i++){
        int m = m0 + ty*4 + (i&3) + ((i>>2)<<6);
        __nv_bfloat16* rowp = zp + (size_t)m*256;
        float* rowz = z32 + (size_t)m*128;
#pragma unroll
        for (int jg=0;jg<2;jg++){
            int n = tx*4 + jg*64;
            const float4 bv = *reinterpret_cast<const float4*>(bias + n);
            float v0 = acc[i][jg*4+0] + bv.x;
            float v1 = acc[i][jg*4+1] + bv.y;
            float v2 = acc[i][jg*4+2] + bv.z;
            float v3 = acc[i][jg*4+3] + bv.w;
            __nv_bfloat16 h0=__float2bfloat16(v0), h1=__float2bfloat16(v1);
            __nv_bfloat16 h2=__float2bfloat16(v2), h3=__float2bfloat16(v3);
            uint2 hv, lv;
            hv.x = pack2bf(h0,h1); hv.y = pack2bf(h2,h3);
            lv.x = pack2bf(__float2bfloat16(v0-__bfloat162float(h0)),
                           __float2bfloat16(v1-__bfloat162float(h1)));
            lv.y = pack2bf(__float2bfloat16(v2-__bfloat162float(h2)),
                           __float2bfloat16(v3-__bfloat162float(h3)));
            *reinterpret_cast<uint2*>(rowp + n)       = hv;
            *reinterpret_cast<uint2*>(rowp + 128 + n) = lv;
            float4 tv;
            tv.x = tf32r(v0); tv.y = tf32r(v1); tv.z = tf32r(v2); tv.w = tf32r(v3);
            *reinterpret_cast<float4*>(rowz + n) = tv;
        }
    }
}

// ---------------- mma primitives ----------------------------------------------
__device__ __forceinline__ void ldmatrix_x4(uint32_t& r0, uint32_t& r1, uint32_t& r2, uint32_t& r3,
                                            uint32_t addr){
    asm volatile("ldmatrix.sync.aligned.m8n8.x4.shared.b16 {%0,%1,%2,%3}, [%4];"
        : "=r"(r0), "=r"(r1), "=r"(r2), "=r"(r3) : "r"(addr));
}
__device__ __forceinline__ void mma16816(float* d, const uint32_t* a, uint32_t b0, uint32_t b1){
    asm volatile("mma.sync.aligned.m16n8k16.row.col.f32.bf16.bf16.f32 "
        "{%0,%1,%2,%3}, {%4,%5,%6,%7}, {%8,%9}, {%0,%1,%2,%3};"
        : "+f"(d[0]), "+f"(d[1]), "+f"(d[2]), "+f"(d[3])
        : "r"(a[0]), "r"(a[1]), "r"(a[2]), "r"(a[3]), "r"(b0), "r"(b1));
}
__device__ __forceinline__ void mma1688tf(float* d, const uint32_t* a, uint32_t b0, uint32_t b1){
    asm volatile("mma.sync.aligned.m16n8k8.row.col.f32.tf32.tf32.f32 "
        "{%0,%1,%2,%3}, {%4,%5,%6,%7}, {%8,%9}, {%0,%1,%2,%3};"
        : "+f"(d[0]), "+f"(d[1]), "+f"(d[2]), "+f"(d[3])
        : "r"(a[0]), "r"(a[1]), "r"(a[2]), "r"(a[3]), "r"(b0), "r"(b1));
}

// ---------------- gi GEMM via mma.sync (3-term split bf16) --------------------
#define PRS 264
#define GI_SMEM_BYTES (2*128*PRS*2)

__global__ void __launch_bounds__(256) gi_mma_kernel(
    const __nv_bfloat16* __restrict__ zp, const __nv_bfloat16* __restrict__ wis,
    const float* __restrict__ bi, float* __restrict__ gi)
{
    extern __shared__ __align__(16) char gsm[];
    __nv_bfloat16* SA = reinterpret_cast<__nv_bfloat16*>(gsm);
    __nv_bfloat16* SB = SA + 128*PRS;
    const uint32_t SAb = smem_u32(SA);
    const uint32_t SBb = smem_u32(SB);

    const int tid  = threadIdx.x;
    const int warp = tid >> 5;
    const int lane = tid & 31;
    const int n0   = blockIdx.x * 128;
    const int m0   = blockIdx.y * 128;

    for (int it = 0; it < 16; it++){
        int idx = tid + it*256;
        int r = idx >> 5, u = idx & 31;
        *reinterpret_cast<uint4*>(SA + r*PRS + u*8) =
            *reinterpret_cast<const uint4*>(zp + (size_t)(m0 + r)*256 + u*8);
        *reinterpret_cast<uint4*>(SB + r*PRS + u*8) =
            *reinterpret_cast<const uint4*>(wis + (size_t)(n0 + r)*256 + u*8);
    }
    __syncthreads();

    const uint32_t lrow = (lane & 7) + ((lane >> 3) & 1)*8;
    const uint32_t lcol = (lane >> 4)*8;
    const int mw = warp * 16;

    uint32_t afr[16][4];
#pragma unroll
    for (int kc = 0; kc < 16; kc++){
        uint32_t addr = SAb + ((mw + lrow)*PRS + kc*16 + lcol)*2;
        ldmatrix_x4(afr[kc][0], afr[kc][1], afr[kc][2], afr[kc][3], addr);
    }

    float acc[16][4];
#pragma unroll
    for (int nf = 0; nf < 16; nf++)
#pragma unroll
        for (int i = 0; i < 4; i++) acc[nf][i] = 0.f;

#pragma unroll
    for (int kc = 0; kc < 16; kc++){
#pragma unroll
        for (int nf2 = 0; nf2 < 8; nf2++){
            uint32_t r0,r1,r2,r3;
            uint32_t addr = SBb + ((nf2*16 + lrow)*PRS + kc*16 + lcol)*2;
            ldmatrix_x4(r0, r1, r2, r3, addr);
            if (kc < 8){
                mma16816(acc[nf2*2+0], afr[kc],   r0, r2);
                mma16816(acc[nf2*2+1], afr[kc],   r1, r3);
                mma16816(acc[nf2*2+0], afr[kc+8], r0, r2);
                mma16816(acc[nf2*2+1], afr[kc+8], r1, r3);
            } else {
                mma16816(acc[nf2*2+0], afr[kc-8], r0, r2);
                mma16816(acc[nf2*2+1], afr[kc-8], r1, r3);
            }
        }
    }

    const int r0g = m0 + mw + (lane >> 2);
#pragma unroll
    for (int nf = 0; nf < 16; nf++){
        int c0 = n0 + nf*8 + (lane & 3)*2;
        float b0 = bi[c0], b1 = bi[c0+1];
#pragma unroll
        for (int rr = 0; rr < 2; rr++){
            float2 v;
            v.x = acc[nf][rr*2+0] + b0;
            v.y = acc[nf][rr*2+1] + b1;
            *reinterpret_cast<float2*>(gi + (size_t)(r0g + rr*8)*768 + c0) = v;
        }
    }
}

// ---------------- GRU scan (proven layout; hoisted mapa addresses) ------------
__device__ __forceinline__ void cluster_sync_all(){
    asm volatile("barrier.cluster.arrive.aligned;" ::: "memory");
    asm volatile("barrier.cluster.wait.aligned;"   ::: "memory");
}

#define GRU_SMEM_FLOATS 28192
#define GRU_SMEM_BYTES  (GRU_SMEM_FLOATS*4)

__global__ void __launch_bounds__(384) __cluster_dims__(8,1,1)
gru_kernel(const float* __restrict__ gi, const float* __restrict__ Wh,
           const float* __restrict__ bhn, __nv_bfloat16* __restrict__ cp_out)
{
    extern __shared__ float sm[];
    float* Whs   = sm;            // [256][96]
    float* h2    = sm + 24576;    // [2][256][4]
    float* part  = sm + 26624;    // [q*4+b][96]
    float* bhn_s = sm + 28160;    // [32]

    const int tid  = threadIdx.x;
    const int rank = blockIdx.x & 7;
    const int b0   = (blockIdx.x >> 3) * 4;
    const int u0   = rank * 32;

    for (int i = tid; i < 256*96; i += 384){
        int u = i / 96, c = i % 96;
        int gcol = (c >> 5)*256 + u0 + (c & 31);
        Whs[i] = Wh[u*768 + gcol];
    }
    for (int i = tid; i < 2048; i += 384) h2[i] = 0.f;
    if (tid < 32) bhn_s[tid] = bhn[u0 + tid];
    __syncthreads();
    cluster_sync_all();

    const int c  = tid % 96;
    const int q  = tid / 96;
    const int b3 = tid >> 5;
    const int ul = tid & 31;

    unsigned ra0[8], ra1[8];
    if (tid < 128){
        unsigned l0 = smem_u32(h2 + (u0+ul)*4 + b3);
        unsigned l1 = l0 + 4096;
#pragma unroll
        for (int r8 = 0; r8 < 8; r8++){
            asm("mapa.shared::cluster.u32 %0, %1, %2;" : "=r"(ra0[r8]) : "r"(l0), "r"(r8));
            asm("mapa.shared::cluster.u32 %0, %1, %2;" : "=r"(ra1[r8]) : "r"(l1), "r"(r8));
        }
    }

    int cur = 0;
    for (int t = 0; t < NT; t++){
        float gir=0.f, giz=0.f, gin=0.f;
        if (tid < 128){
            const float* gp = gi + ((size_t)(b0+b3)*NT + t)*768;
            gir = gp[u0+ul]; giz = gp[256+u0+ul]; gin = gp[512+u0+ul];
        }
        {
            const float* hb = h2 + cur*1024;
            float a0=0.f,a1=0.f,a2=0.f,a3=0.f;
            const int ub = q*64;
#pragma unroll 8
            for (int uu = 0; uu < 64; uu++){
                int u = ub + uu;
                float w = Whs[u*96 + c];
                float4 h4 = *reinterpret_cast<const float4*>(hb + u*4);
                a0 += w*h4.x; a1 += w*h4.y; a2 += w*h4.z; a3 += w*h4.w;
            }
            part[(q*4+0)*96 + c] = a0;
            part[(q*4+1)*96 + c] = a1;
            part[(q*4+2)*96 + c] = a2;
            part[(q*4+3)*96 + c] = a3;
        }
        __syncthreads();

        int nxt = cur ^ 1;
        if (tid < 128){
            float hr = part[(0*4+b3)*96 + ul]      + part[(1*4+b3)*96 + ul]
                     + part[(2*4+b3)*96 + ul]      + part[(3*4+b3)*96 + ul];
            float hz = part[(0*4+b3)*96 + 32 + ul] + part[(1*4+b3)*96 + 32 + ul]
                     + part[(2*4+b3)*96 + 32 + ul] + part[(3*4+b3)*96 + 32 + ul];
            float hn = part[(0*4+b3)*96 + 64 + ul] + part[(1*4+b3)*96 + 64 + ul]
                     + part[(2*4+b3)*96 + 64 + ul] + part[(3*4+b3)*96 + 64 + ul];
            float r  = 1.f/(1.f + expf(-(gir + hr)));
            float zz = 1.f/(1.f + expf(-(giz + hz)));
            float n  = tanhf(gin + r*(hn + bhn_s[ul]));
            float hp = h2[cur*1024 + (u0+ul)*4 + b3];
            float hnew = (1.f - zz)*n + zz*hp;
            int g = u0 + ul;
            size_t base = (((size_t)(b0+b3)*NT + t))*512 + (size_t)(g>>7)*256 + (g & 127);
            __nv_bfloat16 hh = __float2bfloat16(hnew);
            cp_out[base]       = hh;
            cp_out[base + 128] = __float2bfloat16(hnew - __bfloat162float(hh));
#pragma unroll
            for (int r8 = 0; r8 < 8; r8++){
                unsigned ad = nxt ? ra1[r8] : ra0[r8];
                asm volatile("st.shared::cluster.f32 [%0], %1;" :: "r"(ad), "f"(hnew) : "memory");
            }
        }
        cluster_sync_all();
        cur = nxt;
    }
}

// ---------------- fused pred(bf16 3-term) + tf32 streaming-softmax loss --------
// Phase 1: unchanged bf16 path (Wp staged 128x264 bf16 in Sbuf, A from global cp).
// Phase 2: TF32 single-pass. Z staged fp32 (tf32-rounded) 64 rows x 132-float
// stride; B-frags via 2 conflict-free LDS.32; A-frags remapped from phase-1
// accumulators with quad shuffles. smem footprint unchanged (67.6KB, 2 CTA/SM).
#define LOSS_RS 264
#define ZRS 132
#define ZT_ROWS 64
#define LOSS_SMEM_BYTES (128*LOSS_RS*2)

__global__ void __launch_bounds__(256,2) loss_fused_kernel(
    const __nv_bfloat16* __restrict__ cp, const __nv_bfloat16* __restrict__ wps,
    const float* __restrict__ bp, const float* __restrict__ z32,
    float* __restrict__ out)
{
    extern __shared__ __align__(16) char lsm[];
    __nv_bfloat16* Sbuf = reinterpret_cast<__nv_bfloat16*>(lsm);
    const uint32_t Sb = smem_u32(Sbuf);
    const uint32_t SZb[2] = { Sb, Sb + ZT_ROWS*ZRS*4 };   // two fp32 Z buffers
    const uint32_t* const Zw0 = reinterpret_cast<const uint32_t*>(lsm);
    __shared__ float wsum[16];

    const int tid  = threadIdx.x;
    const int warp = tid >> 5;
    const int lane = tid & 31;
    const int b    = blockIdx.y;
    const int k    = blockIdx.z + 1;
    const int t0   = blockIdx.x * 128;
    const int Tm   = NT - k;
    const int kk   = k - 1;
    const int mg   = b*NT + t0;

    const uint32_t lrow = (lane & 7) + ((lane >> 3) & 1)*8;
    const uint32_t lcol = (lane >> 4)*8;
    const int mw = warp * 16;

    // ================= Phase 1: pred A-tile (bf16 3-term, unchanged) ==========
    float acc[16][4];
#pragma unroll
    for (int nf = 0; nf < 16; nf++)
#pragma unroll
        for (int i = 0; i < 4; i++) acc[nf][i] = 0.f;

    for (int khalf = 0; khalf < 2; khalf++){
        for (int it = 0; it < 16; it++){
            int idx = tid + it*256;
            int r = idx >> 5, u = idx & 31;
            *reinterpret_cast<uint4*>(Sbuf + r*LOSS_RS + u*8) =
                *reinterpret_cast<const uint4*>(wps + ((size_t)khalf*1536 + kk*128 + r)*256 + u*8);
        }
        __syncthreads();

        const char* cb = reinterpret_cast<const char*>(
            cp + (size_t)(mg + mw + (lane >> 2))*512 + khalf*256 + (lane & 3)*2);
        const size_t row8 = 8*512*2;

#pragma unroll
        for (int kc = 0; kc < 8; kc++){
            uint32_t ahi[4], alo[4];
            const char* ph = cb + (kc*16)*2;
            const char* pl = cb + ((kc+8)*16)*2;
            ahi[0] = *reinterpret_cast<const uint32_t*>(ph);
            ahi[1] = *reinterpret_cast<const uint32_t*>(ph + row8);
            ahi[2] = *reinterpret_cast<const uint32_t*>(ph + 16);
            ahi[3] = *reinterpret_cast<const uint32_t*>(ph + row8 + 16);
            alo[0] = *reinterpret_cast<const uint32_t*>(pl);
            alo[1] = *reinterpret_cast<const uint32_t*>(pl + row8);
            alo[2] = *reinterpret_cast<const uint32_t*>(pl + 16);
            alo[3] = *reinterpret_cast<const uint32_t*>(pl + row8 + 16);
#pragma unroll
            for (int nf2 = 0; nf2 < 8; nf2++){
                uint32_t r0,r1,r2,r3;
                uint32_t addr = Sb + ((nf2*16 + lrow)*LOSS_RS + kc*16 + lcol)*2;
                ldmatrix_x4(r0, r1, r2, r3, addr);
                mma16816(acc[nf2*2+0], ahi, r0, r2);
                mma16816(acc[nf2*2+1], ahi, r1, r3);
                mma16816(acc[nf2*2+0], alo, r0, r2);
                mma16816(acc[nf2*2+1], alo, r1, r3);
                addr = Sb + ((nf2*16 + lrow)*LOSS_RS + (kc+8)*16 + lcol)*2;
                ldmatrix_x4(r0, r1, r2, r3, addr);
                mma16816(acc[nf2*2+0], ahi, r0, r2);
                mma16816(acc[nf2*2+1], ahi, r1, r3);
            }
        }
        __syncthreads();
    }

    // ---- issue Z tile 0 prefetch (64 fp32 rows of 128 floats) ----
    for (int it = 0; it < 8; it++){
        int idx = tid + it*256;            // 2048 16B units
        int j = idx >> 5, u = idx & 31;
        int jr = k + j;
        uint32_t ok = (jr < NT) ? 16u : 0u;
        int jc = jr < NT ? jr : NT-1;
        cp_async16(SZb[0] + (uint32_t)(j*ZRS + u*4)*4,
                   z32 + ((size_t)(b*NT) + jc)*128 + u*4, ok);
    }
    CP_COMMIT();

    // ---- bias + scale, then remap accumulators -> tf32 A-fragments ----
    uint32_t afr[16][4];
    {
        const int q   = lane & 3;
        const int ct2 = q*2;
#pragma unroll
        for (int nf = 0; nf < 16; nf++){
            float b0 = bp[kk*128 + nf*8 + ct2];
            float b1 = bp[kk*128 + nf*8 + ct2 + 1];
            acc[nf][0] = (acc[nf][0] + b0) * INV_TEMP;
            acc[nf][1] = (acc[nf][1] + b1) * INV_TEMP;
            acc[nf][2] = (acc[nf][2] + b0) * INV_TEMP;
            acc[nf][3] = (acc[nf][3] + b1) * INV_TEMP;
        }
        const int sA = (lane & ~3) + (q >> 1);
        const int sB = sA + 2;
        const bool odd = (q & 1);
#pragma unroll
        for (int kc = 0; kc < 16; kc++){
            float g0 = __shfl_sync(0xFFFFFFFFu, acc[kc][0], sA);
            float g1 = __shfl_sync(0xFFFFFFFFu, acc[kc][1], sA);
            float h0 = __shfl_sync(0xFFFFFFFFu, acc[kc][2], sA);
            float h1 = __shfl_sync(0xFFFFFFFFu, acc[kc][3], sA);
            float g2 = __shfl_sync(0xFFFFFFFFu, acc[kc][0], sB);
            float g3 = __shfl_sync(0xFFFFFFFFu, acc[kc][1], sB);
            float h2 = __shfl_sync(0xFFFFFFFFu, acc[kc][2], sB);
            float h3 = __shfl_sync(0xFFFFFFFFu, acc[kc][3], sB);
            afr[kc][0] = f2tf32(odd ? g1 : g0);   // (gr,     col q)
            afr[kc][1] = f2tf32(odd ? h1 : h0);   // (gr+8,   col q)
            afr[kc][2] = f2tf32(odd ? g3 : g2);   // (gr,     col q+4)
            afr[kc][3] = f2tf32(odd ? h3 : h2);   // (gr+8,   col q+4)
        }
    }

    // ================= Phase 2: tf32 streaming softmax (8 x 64-row tiles) =====
    const int ra = t0 + mw + (lane >> 2);
    const bool rv0 = ra < Tm, rv1 = (ra + 8) < Tm;
    float mr[2] = {-1e30f, -1e30f};
    float sr[2] = {0.f, 0.f};
    float tot = 0.f;

    for (int jt = 0; jt < 8; jt++){
        const int j0 = jt * ZT_ROWS;
        CP_WAIT0();
        __syncthreads();
        if (jt < 7){
            const int jn = (jt+1) * ZT_ROWS;
            const uint32_t dst = SZb[(jt+1) & 1];
            for (int it = 0; it < 8; it++){
                int idx = tid + it*256;
                int j = idx >> 5, u = idx & 31;
                int jr = k + jn + j;
                uint32_t ok = (jr < NT) ? 16u : 0u;
                int jc = jr < NT ? jr : NT-1;
                cp_async16(dst + (uint32_t)(j*ZRS + u*4)*4,
                           z32 + ((size_t)(b*NT) + jc)*128 + u*4, ok);
            }
            CP_COMMIT();
        }
        const uint32_t* Zw = Zw0 + (jt & 1) * (ZT_ROWS*ZRS);

        // per-nf row pointers (row j = nf*8 + lane/4, col offset lane%3..)
        const uint32_t* rowp[8];
#pragma unroll
        for (int nf = 0; nf < 8; nf++)
            rowp[nf] = Zw + (uint32_t)((nf*8 + (lane>>2))*ZRS + (lane & 3));

        float lac[8][4];
#pragma unroll
        for (int nf = 0; nf < 8; nf++)
#pragma unroll
            for (int i = 0; i < 4; i++) lac[nf][i] = 0.f;

#pragma unroll
        for (int kc = 0; kc < 16; kc++){
#pragma unroll
            for (int nf = 0; nf < 8; nf++){
                uint32_t b0 = rowp[nf][kc*8];
                uint32_t b1 = rowp[nf][kc*8 + 4];
                mma1688tf(lac[nf], afr[kc], b0, b1);
            }
        }

        if (j0 + ZT_ROWS <= Tm){
            float tm[2] = {-1e30f, -1e30f};
#pragma unroll
            for (int nf = 0; nf < 8; nf++){
                tm[0] = fmaxf(tm[0], fmaxf(lac[nf][0], lac[nf][1]));
                tm[1] = fmaxf(tm[1], fmaxf(lac[nf][2], lac[nf][3]));
            }
#pragma unroll
            for (int o = 1; o <= 2; o <<= 1){
                tm[0] = fmaxf(tm[0], __shfl_xor_sync(0xFFFFFFFFu, tm[0], o));
                tm[1] = fmaxf(tm[1], __shfl_xor_sync(0xFFFFFFFFu, tm[1], o));
            }
#pragma unroll
            for (int rr = 0; rr < 2; rr++){
                float nm = fmaxf(mr[rr], tm[rr]);
                sr[rr] *= __expf(mr[rr] - nm);
                mr[rr] = nm;
            }
            float ls0 = 0.f, ls1 = 0.f, lt0 = 0.f, lt1 = 0.f;
#pragma unroll
            for (int nf = 0; nf < 8; nf++){
                ls0 += __expf(lac[nf][0] - mr[0]) + __expf(lac[nf][1] - mr[0]);
                ls1 += __expf(lac[nf][2] - mr[1]) + __expf(lac[nf][3] - mr[1]);
                lt0 += lac[nf][0] + lac[nf][1];
                lt1 += lac[nf][2] + lac[nf][3];
            }
            sr[0] += ls0; sr[1] += ls1;
            if (rv0) tot += lt0;
            if (rv1) tot += lt1;
        } else {
            const int cbase = j0 + (lane & 3)*2;
            float tm[2] = {-1e30f, -1e30f};
#pragma unroll
            for (int nf = 0; nf < 8; nf++){
                int c0 = cbase + nf*8;
                bool v0 = c0 < Tm, v1 = (c0+1) < Tm;
                if (v0){ tm[0] = fmaxf(tm[0], lac[nf][0]); tm[1] = fmaxf(tm[1], lac[nf][2]); }
                if (v1){ tm[0] = fmaxf(tm[0], lac[nf][1]); tm[1] = fmaxf(tm[1], lac[nf][3]); }
            }
#pragma unroll
            for (int o = 1; o <= 2; o <<= 1){
                tm[0] = fmaxf(tm[0], __shfl_xor_sync(0xFFFFFFFFu, tm[0], o));
                tm[1] = fmaxf(tm[1], __shfl_xor_sync(0xFFFFFFFFu, tm[1], o));
            }
            if (tm[0] > -1e29f){
#pragma unroll
                for (int rr = 0; rr < 2; rr++){
                    float nm = fmaxf(mr[rr], tm[rr]);
                    sr[rr] *= __expf(mr[rr] - nm);
                    mr[rr] = nm;
                }
                float ls0 = 0.f, ls1 = 0.f, lt0 = 0.f, lt1 = 0.f;
#pragma unroll
                for (int nf = 0; nf < 8; nf++){
                    int c0 = cbase + nf*8;
#pragma unroll
                    for (int h = 0; h < 2; h++){
                        if (c0 + h < Tm){
                            ls0 += __expf(lac[nf][h]   - mr[0]);
                            ls1 += __expf(lac[nf][2+h] - mr[1]);
                            lt0 += lac[nf][h]; lt1 += lac[nf][2+h];
                        }
                    }
                }
                sr[0] += ls0; sr[1] += ls1;
                if (rv0) tot += lt0;
                if (rv1) tot += lt1;
            }
        }
        __syncthreads();
    }

    // ---- finalize ----
#pragma unroll
    for (int o = 1; o <= 2; o <<= 1){
        sr[0] += __shfl_xor_sync(0xFFFFFFFFu, sr[0], o);
        sr[1] += __shfl_xor_sync(0xFFFFFFFFu, sr[1], o);
    }
    float lse = 0.f;
    if ((lane & 3) == 0){
        if (rv0) lse += mr[0] + __logf(sr[0]);
        if (rv1) lse += mr[1] + __logf(sr[1]);
    }
#pragma unroll
    for (int o = 16; o; o >>= 1){
        lse += __shfl_xor_sync(0xFFFFFFFFu, lse, o);
        tot += __shfl_xor_sync(0xFFFFFFFFu, tot, o);
    }
    if (lane == 0){ wsum[warp] = lse; wsum[8+warp] = tot; }
    __syncthreads();
    if (tid == 0){
        float L = 0.f, T = 0.f;
#pragma unroll
        for (int w = 0; w < 8; w++){ L += wsum[w]; T += wsum[8+w]; }
        float inv = 1.0f / ((float)NB * (float)Tm * (float)NK);
        atomicAdd(out, L*inv - T*(inv/(float)Tm));
    }
}

// ---------------- launch ------------------------------------------------------
extern "C" void kernel_launch(void* const* d_in, const int* in_sizes, int n_in,
                              void* d_out, int out_size)
{
    const float* x_seq  = (const float*)d_in[0];
    const float* W_enc  = (const float*)d_in[1];
    const float* b_enc  = (const float*)d_in[2];
    const float* W_proj = (const float*)d_in[3];
    const float* b_proj = (const float*)d_in[4];
    const float* Wi     = (const float*)d_in[5];
    const float* bi     = (const float*)d_in[6];
    const float* Wh     = (const float*)d_in[7];
    const float* bhn    = (const float*)d_in[8];
    const float* Wp     = (const float*)d_in[9];
    const float* bp     = (const float*)d_in[10];
    float* out = (float*)d_out;

    float *Wf, *bz, *gibuf, *z32b;
    __nv_bfloat16 *zpb, *cpb, *wpsb, *wisb;
    cudaGetSymbolAddress((void**)&Wf,    g_Wf);
    cudaGetSymbolAddress((void**)&bz,    g_bz);
    cudaGetSymbolAddress((void**)&gibuf, g_gi);
    cudaGetSymbolAddress((void**)&z32b,  g_z32);
    cudaGetSymbolAddress((void**)&zpb,   g_zp);
    cudaGetSymbolAddress((void**)&cpb,   g_cp);
    cudaGetSymbolAddress((void**)&wpsb,  g_wps);
    cudaGetSymbolAddress((void**)&wisb,  g_wis);

    cudaFuncSetAttribute(gru_kernel,        cudaFuncAttributeMaxDynamicSharedMemorySize, GRU_SMEM_BYTES);
    cudaFuncSetAttribute(loss_fused_kernel, cudaFuncAttributeMaxDynamicSharedMemorySize, LOSS_SMEM_BYTES);
    cudaFuncSetAttribute(gi_mma_kernel,     cudaFuncAttributeMaxDynamicSharedMemorySize, GI_SMEM_BYTES);

    // 1: prep (repack Wi/Wp + Wf gemm + bz + loss zero)
    prep_kernel<<<PREP_REPACK_BLOCKS + 3, 512>>>(
        Wi, wisb, Wp, wpsb, b_enc, W_proj, b_proj, bz, out, W_enc, Wf);
    // 2: z = x @ Wf + bz -> split-bf16 zp + tf32-rounded z32
    zgemm_pack_kernel<<<dim3(1,256), 256>>>(x_seq, Wf, bz, zpb, z32b);
    // 3: gi = z @ Wi + bi  (tensor path)
    gi_mma_kernel<<<dim3(6,256), 256, GI_SMEM_BYTES>>>(zpb, wisb, bi, gibuf);
    // 4: GRU scan (persistent, clustered)
    gru_kernel<<<128, 384, GRU_SMEM_BYTES>>>(gibuf, Wh, bhn, cpb);
    // 5: fused pred(bf16 3-term) + tf32 single-pass streaming-softmax loss
    loss_fused_kernel<<<dim3(4,64,12), 256, LOSS_SMEM_BYTES>>>(cpb, wpsb, bp, z32b, out);
}